// round 5
// baseline (speedup 1.0000x reference)
#include <cuda_runtime.h>
#include <math.h>

#define TILE 32
#define IMG_H 512
#define IMG_W 512
#define NTHREADS 256

typedef unsigned long long ull;

__device__ double g_acc;

__global__ void init_acc_kernel() { g_acc = 0.0; }

__global__ void finalize_kernel(float* out, double scale) {
    out[0] = (float)(g_acc * scale);
}

// ---- f32x2 packed helpers ----
__device__ __forceinline__ ull pack2(float lo, float hi) {
    ull r;
    asm("mov.b64 %0, {%1, %2};" : "=l"(r) : "f"(lo), "f"(hi));
    return r;
}
__device__ __forceinline__ void unpack2(ull v, float& lo, float& hi) {
    asm("mov.b64 {%0, %1}, %2;" : "=f"(lo), "=f"(hi) : "l"(v));
}
__device__ __forceinline__ void ffma2(ull& d, ull a, ull b) {
    asm("fma.rn.f32x2 %0, %1, %2, %0;" : "+l"(d) : "l"(a), "l"(b));
}
__device__ __forceinline__ ull fma2v(ull a, ull b, ull c) {   // a*b + c
    ull d;
    asm("fma.rn.f32x2 %0, %1, %2, %3;" : "=l"(d) : "l"(a), "l"(b), "l"(c));
    return d;
}
__device__ __forceinline__ ull mul2(ull a, ull b) {
    ull d;
    asm("mul.rn.f32x2 %0, %1, %2;" : "=l"(d) : "l"(a), "l"(b));
    return d;
}

// shared-memory layout (bytes); all sections 16B-aligned
__host__ __device__ constexpr int smem_bytes_xs(int K) {
    int R = K / 2, XS = TILE + 4 * R;
    return XS * (XS + 1) * 8;
}
__host__ __device__ constexpr int smem_bytes_b(int K) {
    int R = K / 2, MS = TILE + 2 * R;
    int hbB = (40 + K - 1) * 41 * 16;    // hb: padded rows, u128 stride 41
    int h2B = MS * 33 * 16;              // h2: u128 stride 33
    return hbB > h2B ? hbB : h2B;
}
__host__ __device__ constexpr int smem_bytes_ms(int K) {
    int R = K / 2, MS = TILE + 2 * R;
    return 40 * (MS + 1) * 8;
}
__host__ __device__ constexpr int smem_bytes_total(int K) {
    return smem_bytes_xs(K) + smem_bytes_b(K) + smem_bytes_ms(K) + 32 * 33 * 8;
}

template <int K>
__global__ __launch_bounds__(NTHREADS, 3)
void stat_loss_kernel(const float* __restrict__ pred,
                      const float* __restrict__ tgt)
{
    constexpr int R    = K / 2;
    constexpr int XS   = TILE + 4 * R;    // x tile side (double halo)
    constexpr int MS   = TILE + 2 * R;    // mean-field side (single halo)
    constexpr int XSP  = XS + 1;          // xs row stride (u64, odd)
    constexpr int HBW  = 41;              // hb row stride (u128, odd)
    constexpr int MSW  = MS + 1;          // ms row stride (u64, odd)
    constexpr int H2W  = 33;              // h2 row stride (u128, odd)
    constexpr int VSW  = 33;              // vs row stride (u64, odd)
    constexpr int QH   = 8 + K - 1;       // taps per 8-wide horizontal group
    constexpr int QV8  = 8 + K - 1;       // taps per 8-row vertical group
    constexpr int QV4  = 4 + K - 1;       // taps per 4-row vertical group

    extern __shared__ __align__(16) unsigned char smem[];
    __shared__ float wsum[NTHREADS / 32];

    ull*        xs = (ull*)smem;                                   // (x_p, x_t)
    ulonglong2* hb = (ulonglong2*)(smem + smem_bytes_xs(K));       // level-1 horiz
    ulonglong2* h2 = (ulonglong2*)(smem + smem_bytes_xs(K));       // level-2 horiz (aliases hb)
    ull*        ms = (ull*)(smem + smem_bytes_xs(K) + smem_bytes_b(K));  // mean pairs
    ull*        vs = (ull*)(smem + smem_bytes_xs(K) + smem_bytes_b(K) + smem_bytes_ms(K)); // var pairs

    const int tid = threadIdx.x;
    const int x0 = blockIdx.x * TILE;
    const int y0 = blockIdx.y * TILE;
    const size_t plane_off = (size_t)blockIdx.z * (size_t)(IMG_H * IMG_W);

    // normalized 1D gaussian, packed
    ull gp[K];
    {
        const float sigma = (float)K / 6.0f;
        const float inv2s2 = 1.0f / (2.0f * sigma * sigma);
        float gtmp[K];
        float s = 0.0f;
#pragma unroll
        for (int j = 0; j < K; ++j) {
            float c = (float)(j - K / 2);
            gtmp[j] = expf(-c * c * inv2s2);
            s += gtmp[j];
        }
        float inv = 1.0f / s;
#pragma unroll
        for (int j = 0; j < K; ++j) { float w = gtmp[j] * inv; gp[j] = pack2(w, w); }
    }
    const ull NEG1 = pack2(-1.0f, -1.0f);

    const bool edge = (x0 < 2 * R) || (y0 < 2 * R) ||
                      (x0 + TILE + 2 * R > IMG_W) || (y0 + TILE + 2 * R > IMG_H);

    // stage mappings (single shot)
    const int s2_row = tid / 5, s2_cx = (tid % 5) * 8;    // XS rows × 5 groups
    const int s3_c = tid % MS, s3_r0 = (tid / MS) * 8;    // MS cols × 5 groups
    const int s4_row = tid >> 2, s4_cx = (tid & 3) * 8;   // MS rows × 4 groups
    const int ocx = tid & 31, org = (tid >> 5) * 4;       // 32 cols × 8 groups

    float acc = 0.0f;

    const float* srcp = pred + plane_off;
    const float* srct = tgt + plane_off;

    // ---- S1: load (pred, tgt) tile with halo 2R, zero outside image ----
    if (!edge) {
        const float* bp = srcp + (size_t)(y0 - 2 * R) * IMG_W + (x0 - 2 * R);
        const float* bt = srct + (size_t)(y0 - 2 * R) * IMG_W + (x0 - 2 * R);
        for (int idx = tid; idx < XS * XS; idx += NTHREADS) {
            int ry = idx / XS, rx = idx - ry * XS;
            xs[ry * XSP + rx] = pack2(bp[ry * IMG_W + rx], bt[ry * IMG_W + rx]);
        }
    } else {
        for (int idx = tid; idx < XS * XS; idx += NTHREADS) {
            int ry = idx / XS, rx = idx - ry * XS;
            int gy = y0 - 2 * R + ry, gx = x0 - 2 * R + rx;
            ull v = 0ull;
            if ((unsigned)gy < (unsigned)IMG_H && (unsigned)gx < (unsigned)IMG_W)
                v = pack2(srcp[gy * IMG_W + gx], srct[gy * IMG_W + gx]);
            xs[ry * XSP + rx] = v;
        }
    }
    __syncthreads();

    // ---- S2: horizontal conv of (x, x^2) for both tensors, 8-wide ----
    if (tid < XS * 5) {
        const ull* xrow = xs + s2_row * XSP + s2_cx;
        ull a1[8], a2[8];
#pragma unroll
        for (int rr = 0; rr < 8; ++rr) { a1[rr] = 0ull; a2[rr] = 0ull; }
#pragma unroll
        for (int q = 0; q < QH; ++q) {
            ull xp = xrow[q];
            ull x2 = mul2(xp, xp);
#pragma unroll
            for (int rr = 0; rr < 8; ++rr) {
                int j = q - rr;
                if (j >= 0 && j < K) { ffma2(a1[rr], gp[j], xp); ffma2(a2[rr], gp[j], x2); }
            }
        }
        ulonglong2* hrow = hb + s2_row * HBW + s2_cx;
#pragma unroll
        for (int rr = 0; rr < 8; ++rr) {
            ulonglong2 o; o.x = a1[rr]; o.y = a2[rr];
            hrow[rr] = o;
        }
    }
    __syncthreads();

    // ---- S3: vertical conv -> mean pairs (ms) + clipped variance pairs (vs) ----
    if (tid < MS * 5) {
        const ulonglong2* hcol = hb + s3_r0 * HBW + s3_c;
        ull a1[8], a2[8];
#pragma unroll
        for (int rr = 0; rr < 8; ++rr) { a1[rr] = 0ull; a2[rr] = 0ull; }
#pragma unroll
        for (int q = 0; q < QV8; ++q) {
            ulonglong2 p = hcol[q * HBW];
#pragma unroll
            for (int rr = 0; rr < 8; ++rr) {
                int j = q - rr;
                if (j >= 0 && j < K) { ffma2(a1[rr], gp[j], p.x); ffma2(a2[rr], gp[j], p.y); }
            }
        }
#pragma unroll
        for (int rr = 0; rr < 8; ++rr) {
            int row = s3_r0 + rr;                   // rows up to 39 (pad: alloc 40)
            ms[row * MSW + s3_c] = a1[rr];
            int vy = row - R, vx = s3_c - R;
            if ((unsigned)vy < 32u && (unsigned)vx < 32u) {
                float mp, mt, sp, st;
                unpack2(a1[rr], mp, mt);
                unpack2(a2[rr], sp, st);
                float vp = fmaxf(sp - mp * mp, 1e-8f);
                float vt = fmaxf(st - mt * mt, 1e-8f);
                vs[vy * VSW + vx] = pack2(vp, vt);
            }
        }
    }
    __syncthreads();

    // ---- S4 (fused): horizontal conv of (xc^3, xc^4), computed per tap ----
    if (tid < MS * 4) {
        const ull* xrow = xs + (s4_row + R) * XSP + (s4_cx + R);
        const ull* mrow = ms + s4_row * MSW + s4_cx;
        ull a3[8], a4[8];
#pragma unroll
        for (int rr = 0; rr < 8; ++rr) { a3[rr] = 0ull; a4[rr] = 0ull; }
        if (!edge) {
#pragma unroll
            for (int q = 0; q < QH; ++q) {
                ull xc  = fma2v(mrow[q], NEG1, xrow[q]);   // x - mean
                ull xc2 = mul2(xc, xc);
                ull c3  = mul2(xc2, xc);
                ull c4  = mul2(xc2, xc2);
#pragma unroll
                for (int rr = 0; rr < 8; ++rr) {
                    int j = q - rr;
                    if (j >= 0 && j < K) { ffma2(a3[rr], gp[j], c3); ffma2(a4[rr], gp[j], c4); }
                }
            }
        } else {
            const int gy = y0 - R + s4_row;
            const bool rowin = (unsigned)gy < (unsigned)IMG_H;
#pragma unroll
            for (int q = 0; q < QH; ++q) {
                int gx = x0 - R + s4_cx + q;
                bool in = rowin && ((unsigned)gx < (unsigned)IMG_W);
                ull xc  = fma2v(mrow[q], NEG1, xrow[q]);
                ull xc2 = mul2(xc, xc);
                ull c3  = in ? mul2(xc2, xc)  : 0ull;
                ull c4  = in ? mul2(xc2, xc2) : 0ull;
#pragma unroll
                for (int rr = 0; rr < 8; ++rr) {
                    int j = q - rr;
                    if (j >= 0 && j < K) { ffma2(a3[rr], gp[j], c3); ffma2(a4[rr], gp[j], c4); }
                }
            }
        }
        ulonglong2* orow = h2 + s4_row * H2W + s4_cx;
#pragma unroll
        for (int rr = 0; rr < 8; ++rr) {
            ulonglong2 o; o.x = a3[rr]; o.y = a4[rr];
            orow[rr] = o;
        }
    }
    __syncthreads();

    // ---- S5: vertical conv -> (m3, m4); features + loss for both tensors ----
    {
        const ulonglong2* hcol = h2 + org * H2W + ocx;
        ull a3[4], a4[4];
#pragma unroll
        for (int rr = 0; rr < 4; ++rr) { a3[rr] = 0ull; a4[rr] = 0ull; }
#pragma unroll
        for (int q = 0; q < QV4; ++q) {
            ulonglong2 p = hcol[q * H2W];
#pragma unroll
            for (int rr = 0; rr < 4; ++rr) {
                int j = q - rr;
                if (j >= 0 && j < K) { ffma2(a3[rr], gp[j], p.x); ffma2(a4[rr], gp[j], p.y); }
            }
        }
#pragma unroll
        for (int rr = 0; rr < 4; ++rr) {
            float m3p, m3t, m4p, m4t;
            unpack2(a3[rr], m3p, m3t);
            unpack2(a4[rr], m4p, m4t);
            float mp, mt, vp, vt;
            unpack2(ms[(org + rr + R) * MSW + (ocx + R)], mp, mt);
            unpack2(vs[(org + rr) * VSW + ocx], vp, vt);
            float sdp = sqrtf(vp), sdt = sqrtf(vt);
            float skp = m3p / (sdp * sdp * sdp + 1e-8f);
            float skt = m3t / (sdt * sdt * sdt + 1e-8f);
            float kup = m4p / (vp * vp + 1e-8f);
            float kut = m4t / (vt * vt + 1e-8f);
            acc += fabsf(mp - mt)
                 + fabsf(vp - vt)
                 + 0.5f   * fabsf(skp - skt)
                 + 0.001f * fabsf(kup - kut);
        }
    }

    // ---- block reduction, atomic accumulate ----
#pragma unroll
    for (int off = 16; off > 0; off >>= 1)
        acc += __shfl_xor_sync(0xffffffffu, acc, off);
    if ((tid & 31) == 0) wsum[tid >> 5] = acc;
    __syncthreads();
    if (tid < 32) {
        float v = (tid < NTHREADS / 32) ? wsum[tid] : 0.0f;
#pragma unroll
        for (int off = 16; off > 0; off >>= 1)
            v += __shfl_xor_sync(0xffffffffu, v, off);
        if (tid == 0) atomicAdd(&g_acc, (double)v);
    }
}

extern "C" void kernel_launch(void* const* d_in, const int* in_sizes, int n_in,
                              void* d_out, int out_size) {
    const float* pred = (const float*)d_in[0];
    const float* tgt  = (const float*)d_in[1];
    float* out = (float*)d_out;

    const int npix = in_sizes[0];                 // 16*3*512*512
    const int planes = npix / (IMG_H * IMG_W);    // 48

    dim3 grid(IMG_W / TILE, IMG_H / TILE, planes);

    // opt-in to >48KB dynamic shared memory (idempotent; not a stream op)
    cudaFuncSetAttribute(stat_loss_kernel<3>, cudaFuncAttributeMaxDynamicSharedMemorySize,
                         smem_bytes_total(3));
    cudaFuncSetAttribute(stat_loss_kernel<5>, cudaFuncAttributeMaxDynamicSharedMemorySize,
                         smem_bytes_total(5));
    cudaFuncSetAttribute(stat_loss_kernel<7>, cudaFuncAttributeMaxDynamicSharedMemorySize,
                         smem_bytes_total(7));

    init_acc_kernel<<<1, 1>>>();
    stat_loss_kernel<3><<<grid, NTHREADS, smem_bytes_total(3)>>>(pred, tgt);
    stat_loss_kernel<5><<<grid, NTHREADS, smem_bytes_total(5)>>>(pred, tgt);
    stat_loss_kernel<7><<<grid, NTHREADS, smem_bytes_total(7)>>>(pred, tgt);

    const double scale = 1.0 / (12.0 * (double)npix);
    finalize_kernel<<<1, 1>>>(out, scale);
}